// round 1
// baseline (speedup 1.0000x reference)
#include <cuda_runtime.h>
#include <math.h>

// GreenTF as an exponentially-windowed IIR filter bank.
// spec[f,t]*SR/scale = z[16t] - alpha^2048 * z[16(t-128)],
// z[n] = sum_{m>=0} wav[n-m] * alpha^m,  alpha = 2^(-1/320) * cis(2*pi*f/16000).
// Per-thread chain over (b,f); stride-16 recurrence r[t] = alpha^16 r[t-1] + P_t.

#define NFREQ   8001
#define NCHAIN  (2 * NFREQ)
#define TOUT    2000
#define TWAV    32000
#define SR_I    16000

__global__ void __launch_bounds__(128, 1)
greentf_kernel(const float* __restrict__ wav, float* __restrict__ out)
{
    int gid = blockIdx.x * 128 + threadIdx.x;
    if (gid >= NCHAIN) return;
    int b = gid / NFREQ;
    int f = gid - b * NFREQ;
    const float* __restrict__ w = wav + b * TWAV;

    const float TWOPI_O = 6.283185307179586f / 16000.0f;

    // Coefficients c_k = rho^k * cis(2*pi*(f*k mod 16000)/16000), k = 0..16.
    // Exact integer phase reduction -> accurate for all f.
    float cr[17], ci[17];
#pragma unroll
    for (int k = 0; k <= 16; ++k) {
        int ph = (f * k) % SR_I;
        float s, c;
        sincosf(TWOPI_O * (float)ph, &s, &c);
        float d = exp2f((float)(-k) * (1.0f / 320.0f));
        cr[k] = c * d;
        ci[k] = s * d;
    }
    const float A16r = cr[16], A16i = ci[16];   // alpha^16

    // alpha^2048 (truncation correction), |alpha^2048| = 2^-6.4
    int ph2 = (2048 * f) % SR_I;
    float s2, c2;
    sincosf(TWOPI_O * (float)ph2, &s2, &c2);
    const float D2048 = exp2f(-2048.0f / 320.0f);
    const float A2r = c2 * D2048, A2i = s2 * D2048;

    // SC = scale / SR = sqrt(8) / sum_{m=0}^{2047} rho^m  (double, once)
    double rho = exp2(-1.0 / 320.0);
    double geo = (1.0 - exp2(-2048.0 / 320.0)) / (1.0 - rho);
    const float SC = (float)(2.8284271247461903 / geo);

    // Ring buffer of r[t-128] (forced to local memory by dynamic index).
    float2 ring[128];
#pragma unroll
    for (int i = 0; i < 128; ++i) ring[i] = make_float2(0.f, 0.f);

    // prev = wav[16(t-1) .. 16(t-1)+15], zero for t=0 (left zero-padding).
    float prev[16];
#pragma unroll
    for (int i = 0; i < 16; ++i) prev[i] = 0.f;

    float rr = 0.f, ri = 0.f;

    float* __restrict__ outs = out + (size_t)gid * TOUT;                          // sspec
    float* __restrict__ outc = out + (size_t)NCHAIN * TOUT + (size_t)gid * TOUT;  // cspec

    for (int t0 = 0; t0 < TOUT; t0 += 4) {
        float obs[4], obc[4];
#pragma unroll
        for (int u = 0; u < 4; ++u) {
            int t = t0 + u;
            // Aligned 16-float block: wav[16t .. 16t+15]
            const float4* blk = (const float4*)(w + 16 * t);
            float4 x0 = blk[0], x1 = blk[1], x2 = blk[2], x3 = blk[3];
            float cur[16] = { x0.x, x0.y, x0.z, x0.w,
                              x1.x, x1.y, x1.z, x1.w,
                              x2.x, x2.y, x2.z, x2.w,
                              x3.x, x3.y, x3.z, x3.w };

            // Q_t = wav[16t]*c0 + sum_{j=0}^{15} prev[j]*c_{16-j}
            // (17-tap aligned window; overlap term removed via r - prev[0] below)
            float qr  = cur[0];   // c0 = (1, 0)
            float qi  = 0.f;
            float qr2 = 0.f, qi2 = 0.f;
#pragma unroll
            for (int j = 0; j < 16; j += 2) {
                qr  = fmaf(prev[j],     cr[16 - j], qr);
                qi  = fmaf(prev[j],     ci[16 - j], qi);
                qr2 = fmaf(prev[j + 1], cr[15 - j], qr2);
                qi2 = fmaf(prev[j + 1], ci[15 - j], qi2);
            }
            qr += qr2;
            qi += qi2;

            // r[t] = A16 * (r[t-1] - prev[0]) + Q_t   (complex; prev[0] is real)
            float tr = rr - prev[0];
            float nr = fmaf(A16r, tr, fmaf(-A16i, ri, qr));
            float ni = fmaf(A16i, tr, fmaf( A16r, ri, qi));
            rr = nr;
            ri = ni;

            // S[t] = r[t] - alpha^2048 * r[t-128]
            int idx = t & 127;
            float2 h = ring[idx];
            ring[idx] = make_float2(rr, ri);
            float Sr = fmaf(-A2r, h.x, fmaf( A2i, h.y, rr));
            float Si = fmaf(-A2i, h.x, fmaf(-A2r, h.y, ri));

            obs[u] = Si * SC;   // sin part
            obc[u] = Sr * SC;   // cos part

#pragma unroll
            for (int i = 0; i < 16; ++i) prev[i] = cur[i];
        }
        *(float4*)(outs + t0) = make_float4(obs[0], obs[1], obs[2], obs[3]);
        *(float4*)(outc + t0) = make_float4(obc[0], obc[1], obc[2], obc[3]);
    }
}

extern "C" void kernel_launch(void* const* d_in, const int* in_sizes, int n_in,
                              void* d_out, int out_size)
{
    (void)in_sizes; (void)n_in; (void)out_size;
    const float* wav = (const float*)d_in[0];   // (2, 32000) fp32
    float* out = (float*)d_out;                 // sspec then cspec, fp32
    int blocks = (NCHAIN + 127) / 128;          // 126
    greentf_kernel<<<blocks, 128>>>(wav, out);
}